// round 14
// baseline (speedup 1.0000x reference)
#include <cuda_runtime.h>
#include <cuda_fp16.h>
#include <math.h>
#include <stdint.h>

#define NN 25000
#define NE 400000
#define DIN 256
#define HID 64
#define NH 8
#define NCLS 32
#define D1 (HID*NH)   // 512

// Scratch (device globals; no allocation allowed)
__device__ __half g_h16[NN * DIN];
__device__ __half g_w1 [D1 * DIN];
__device__ __half g_w2 [D1 * D1];
__device__ __half g_w3 [NCLS * D1];
__device__ __half g_z16[NN * D1];
__device__ __half g_x16[NN * D1];
__device__ float  g_z3 [NN * NCLS];
__device__ float  g_el [NN * NH];
__device__ float  g_er [NN * NH];
__device__ int    g_offs[NN + 1];

// ---------------------------------------------------------------------------
__global__ void convert_all(const float* __restrict__ h,  const float* __restrict__ W1,
                            const float* __restrict__ W2, const float* __restrict__ W3,
                            __half* __restrict__ h16, __half* __restrict__ w1,
                            __half* __restrict__ w2,  __half* __restrict__ w3) {
    const int n0 = NN * DIN / 2, n1 = D1 * DIN / 2, n2 = D1 * D1 / 2, n3 = NCLS * D1 / 2;
    const int total = n0 + n1 + n2 + n3;
    int i = blockIdx.x * blockDim.x + threadIdx.x;
    int stride = gridDim.x * blockDim.x;
    for (; i < total; i += stride) {
        const float2* s; __half2* d; int j;
        if (i < n0)                { s = (const float2*)h;  d = (__half2*)h16; j = i; }
        else if (i < n0 + n1)      { s = (const float2*)W1; d = (__half2*)w1;  j = i - n0; }
        else if (i < n0 + n1 + n2) { s = (const float2*)W2; d = (__half2*)w2;  j = i - n0 - n1; }
        else                       { s = (const float2*)W3; d = (__half2*)w3;  j = i - n0 - n1 - n2; }
        float2 v = s[j];
        d[j] = __floats2half2_rn(v.x, v.y);
    }
}

// ---------------------------------------------------------------------------
__global__ void build_offsets(const int* __restrict__ dst, int E, int N,
                              int* __restrict__ offs) {
    int n = blockIdx.x * blockDim.x + threadIdx.x;
    if (n > N) return;
    int lo = 0, hi = E;
    while (lo < hi) {
        int mid = (lo + hi) >> 1;
        if (dst[mid] < n) lo = mid + 1; else hi = mid;
    }
    offs[n] = lo;
}

// ---------------------------------------------------------------------------
// FP16 tensor-core NT GEMM: 128x64x64 tile, 8 warps (4m x 2n), warp tile
// 32x32, mma.m16n8k16, ldmatrix frag loads, 3-STAGE cp.async pipeline.
// MODE 1: fp16 C16 + fused per-head el/er (head = blockIdx.x).
// MODE 2: fp32 C32 + fused class-attn el/er (layer 3, N=32).
// ---------------------------------------------------------------------------
__device__ __forceinline__ void cpasync16h(uint32_t smem, const __half* g, bool pred) {
    int sz = pred ? 16 : 0;
    asm volatile("cp.async.cg.shared.global [%0], [%1], 16, %2;\n"
                 :: "r"(smem), "l"(g), "r"(sz));
}

__device__ __forceinline__ void ldsm_x4(uint32_t& r0, uint32_t& r1,
                                        uint32_t& r2, uint32_t& r3, uint32_t addr) {
    asm volatile("ldmatrix.sync.aligned.m8n8.x4.shared.b16 {%0,%1,%2,%3}, [%4];"
                 : "=r"(r0), "=r"(r1), "=r"(r2), "=r"(r3) : "r"(addr));
}

#define AS_STRIDE (128 * 72)
#define BS_STRIDE (64 * 72)
#define GEMM16_SMEM ((3 * AS_STRIDE + 3 * BS_STRIDE) * 2)   // 82944 bytes

template <int MODE>
__global__ void __launch_bounds__(256)
gemm_nt_f16(const __half* __restrict__ A, const __half* __restrict__ B,
            __half* __restrict__ C16, float* __restrict__ C32,
            const float* __restrict__ al, const float* __restrict__ ar,
            float* __restrict__ el, float* __restrict__ er,
            int M, int N, int K) {
    extern __shared__ __half sm16[];
    __half* As = sm16;                     // [3][128*72]
    __half* Bs = sm16 + 3 * AS_STRIDE;     // [3][64*72]
    __shared__ float sred[4][128];

    const int tid  = threadIdx.x;
    const int lane = tid & 31;
    const int wid  = tid >> 5;
    const int wm   = wid & 3;
    const int wn   = wid >> 2;
    const int m0   = blockIdx.y * 128;
    const int n0   = blockIdx.x * 64;
    const int g    = lane >> 2;
    const int tg   = lane & 3;

    const uint32_t sA = (uint32_t)__cvta_generic_to_shared(As);
    const uint32_t sB = (uint32_t)__cvta_generic_to_shared(Bs);

    const int aoff0 = (wm * 32 + (lane & 15)) * 72 + ((lane >> 4) << 3);
    const int boff0 = (wn * 32 + (lane & 7) + ((lane >> 4) << 3)) * 72 + (((lane >> 3) & 1) << 3);

    float c[2][4][4];
#pragma unroll
    for (int im = 0; im < 2; im++)
#pragma unroll
        for (int in = 0; in < 4; in++)
#pragma unroll
            for (int k = 0; k < 4; k++) c[im][in][k] = 0.f;

    const int rA = tid >> 3;
    const int kq = (tid & 7) * 8;

    auto load_tile = [&](int buf, int k0) {
#pragma unroll
        for (int it = 0; it < 4; it++) {
            int r  = rA + it * 32;
            int gm = m0 + r;
            cpasync16h(sA + (uint32_t)(buf * AS_STRIDE + r * 72 + kq) * 2,
                       A + (size_t)gm * K + k0 + kq, gm < M);
        }
#pragma unroll
        for (int it = 0; it < 2; it++) {
            int r  = rA + it * 32;
            int gn = n0 + r;
            cpasync16h(sB + (uint32_t)(buf * BS_STRIDE + r * 72 + kq) * 2,
                       B + (size_t)gn * K + k0 + kq, gn < N);
        }
        asm volatile("cp.async.commit_group;\n");
    };

    const int T = K >> 6;
    load_tile(0, 0);
    if (T > 1) load_tile(1, 64);

    int buf = 0;
    for (int t = 0; t < T; t++) {
        if (t + 2 < T) {
            int nb = buf + 2; if (nb >= 3) nb -= 3;
            load_tile(nb, (t + 2) << 6);
        }
        int rem = T - t - 1;
        if (rem >= 2)      asm volatile("cp.async.wait_group 2;\n");
        else if (rem == 1) asm volatile("cp.async.wait_group 1;\n");
        else               asm volatile("cp.async.wait_group 0;\n");
        __syncthreads();

        const uint32_t aBase = sA + (uint32_t)(buf * AS_STRIDE + aoff0) * 2;
        const uint32_t bBase = sB + (uint32_t)(buf * BS_STRIDE + boff0) * 2;
#pragma unroll
        for (int kk = 0; kk < 64; kk += 16) {
            uint32_t a[2][4];
#pragma unroll
            for (int im = 0; im < 2; im++)
                ldsm_x4(a[im][0], a[im][1], a[im][2], a[im][3],
                        aBase + (uint32_t)(im * 16 * 72 + kk) * 2);
            uint32_t b[4][2];
#pragma unroll
            for (int p = 0; p < 2; p++)
                ldsm_x4(b[2 * p][0], b[2 * p][1], b[2 * p + 1][0], b[2 * p + 1][1],
                        bBase + (uint32_t)(p * 16 * 72 + kk) * 2);
#pragma unroll
            for (int im = 0; im < 2; im++)
#pragma unroll
                for (int in = 0; in < 4; in++) {
                    asm volatile(
                        "mma.sync.aligned.m16n8k16.row.col.f32.f16.f16.f32 "
                        "{%0,%1,%2,%3}, {%4,%5,%6,%7}, {%8,%9}, {%0,%1,%2,%3};\n"
                        : "+f"(c[im][in][0]), "+f"(c[im][in][1]),
                          "+f"(c[im][in][2]), "+f"(c[im][in][3])
                        : "r"(a[im][0]), "r"(a[im][1]), "r"(a[im][2]), "r"(a[im][3]),
                          "r"(b[in][0]), "r"(b[in][1]));
                }
        }
        __syncthreads();
        if (++buf == 3) buf = 0;
    }

    // ---- store C ----
#pragma unroll
    for (int im = 0; im < 2; im++) {
        int r0 = m0 + wm * 32 + im * 16 + g;
#pragma unroll
        for (int in = 0; in < 4; in++) {
            int gn = n0 + wn * 32 + in * 8 + 2 * tg;
            if (gn >= N) continue;
            if (MODE == 1) {
                if (r0 < M)
                    *(__half2*)(C16 + (size_t)r0 * N + gn) =
                        __floats2half2_rn(c[im][in][0], c[im][in][1]);
                if (r0 + 8 < M)
                    *(__half2*)(C16 + (size_t)(r0 + 8) * N + gn) =
                        __floats2half2_rn(c[im][in][2], c[im][in][3]);
            } else {
                if (r0 < M)
                    *(float2*)(C32 + (size_t)r0 * N + gn) =
                        make_float2(c[im][in][0], c[im][in][1]);
                if (r0 + 8 < M)
                    *(float2*)(C32 + (size_t)(r0 + 8) * N + gn) =
                        make_float2(c[im][in][2], c[im][in][3]);
            }
        }
    }

    // ---- fused el/er ----
    {
        const int F = (MODE == 1) ? HID : NCLS;
        const int h = (MODE == 1) ? blockIdx.x : 0;
        float elp[2][2], erp[2][2];
#pragma unroll
        for (int im = 0; im < 2; im++) {
            elp[im][0] = elp[im][1] = 0.f;
            erp[im][0] = erp[im][1] = 0.f;
        }
#pragma unroll
        for (int in = 0; in < 4; in++) {
            int cf = wn * 32 + in * 8 + 2 * tg;
            float a0 = 0.f, a1 = 0.f, b0 = 0.f, b1 = 0.f;
            if (cf < F) {
                a0 = al[h * F + cf]; a1 = al[h * F + cf + 1];
                b0 = ar[h * F + cf]; b1 = ar[h * F + cf + 1];
            }
#pragma unroll
            for (int im = 0; im < 2; im++) {
                elp[im][0] = fmaf(c[im][in][0], a0, fmaf(c[im][in][1], a1, elp[im][0]));
                elp[im][1] = fmaf(c[im][in][2], a0, fmaf(c[im][in][3], a1, elp[im][1]));
                erp[im][0] = fmaf(c[im][in][0], b0, fmaf(c[im][in][1], b1, erp[im][0]));
                erp[im][1] = fmaf(c[im][in][2], b0, fmaf(c[im][in][3], b1, erp[im][1]));
            }
        }
#pragma unroll
        for (int o = 1; o <= 2; o <<= 1) {
#pragma unroll
            for (int im = 0; im < 2; im++) {
#pragma unroll
                for (int r = 0; r < 2; r++) {
                    elp[im][r] += __shfl_xor_sync(0xffffffffu, elp[im][r], o);
                    erp[im][r] += __shfl_xor_sync(0xffffffffu, erp[im][r], o);
                }
            }
        }
        if (tg == 0) {
#pragma unroll
            for (int im = 0; im < 2; im++) {
#pragma unroll
                for (int r = 0; r < 2; r++) {
                    int row = wm * 32 + im * 16 + r * 8 + g;
                    sred[wn][row]     = elp[im][r];
                    sred[2 + wn][row] = erp[im][r];
                }
            }
        }
        __syncthreads();
        if (tid < 128) {
            int gm = m0 + tid;
            if (gm < M) {
                float ev = sred[0][tid] + sred[1][tid];
                float rv = sred[2][tid] + sred[3][tid];
                if (MODE == 1) { el[gm * NH + h] = ev; er[gm * NH + h] = rv; }
                else           { el[gm] = ev;          er[gm] = rv; }
            }
        }
    }
}

// ---------------------------------------------------------------------------
// Edge softmax + aggregation over fp16 z (R10 layout) with SOFTWARE-PIPELINED
// batches: next batch's src + el gathers issued before current batch compute.
// ---------------------------------------------------------------------------
__device__ __forceinline__ void acc8(float* acc, uint4 q, float w) {
    const __half2* hp = (const __half2*)&q;
#pragma unroll
    for (int t = 0; t < 4; t++) {
        float2 f = __half22float2(hp[t]);
        acc[2 * t]     = fmaf(w, f.x, acc[2 * t]);
        acc[2 * t + 1] = fmaf(w, f.y, acc[2 * t + 1]);
    }
}
__device__ __forceinline__ void hmul4(__half2* hacc, uint4 q, uint32_t wu) {
    __half2 w2 = *(__half2*)&wu;
    const __half2* hp = (const __half2*)&q;
#pragma unroll
    for (int t = 0; t < 4; t++) hacc[t] = __hmul2(w2, hp[t]);
}
__device__ __forceinline__ void hfma4(__half2* hacc, uint4 q, uint32_t wu) {
    __half2 w2 = *(__half2*)&wu;
    const __half2* hp = (const __half2*)&q;
#pragma unroll
    for (int t = 0; t < 4; t++) hacc[t] = __hfma2(w2, hp[t], hacc[t]);
}
__device__ __forceinline__ void promote4(float* acc, const __half2* hacc) {
#pragma unroll
    for (int t = 0; t < 4; t++) {
        float2 f = __half22float2(hacc[t]);
        acc[2 * t]     += f.x;
        acc[2 * t + 1] += f.y;
    }
}

__global__ void __launch_bounds__(256, 4)
gat_edge_all(const int* __restrict__ src, const int* __restrict__ offs,
             const float* __restrict__ el, const float* __restrict__ er,
             const __half* __restrict__ z16, __half* __restrict__ xout, int N) {
    const int n    = blockIdx.x * 8 + (threadIdx.x >> 5);
    const int lane = threadIdx.x & 31;
    if (n >= N) return;
    const int s = offs[n], e = offs[n + 1];

    if (s == e) {
        uint4 zq = make_uint4(0, 0, 0, 0);
#pragma unroll
        for (int j = 0; j < 2; j++)
            *(uint4*)(xout + (size_t)n * D1 + j * 256 + 8 * lane) = zq;
        return;
    }

    const float er_h = (lane < 8) ? er[n * NH + lane] : 0.f;
    const int   lh   = lane & 7;
    const int   hsel = lane >> 3;
    const uint4* zb  = (const uint4*)z16;

    float acc[2][8];
#pragma unroll
    for (int j = 0; j < 2; j++)
#pragma unroll
        for (int t = 0; t < 8; t++) acc[j][t] = 0.f;
    float den = 0.f;

    int i = s;
    bool have = (i + 4 <= e);
    int   cs0 = 0, cs1 = 0, cs2 = 0, cs3 = 0;
    float ce0 = 0.f, ce1 = 0.f, ce2 = 0.f, ce3 = 0.f;
    if (have) {
        cs0 = __ldg(src + i);     cs1 = __ldg(src + i + 1);
        cs2 = __ldg(src + i + 2); cs3 = __ldg(src + i + 3);
        ce0 = __ldg(el + cs0 * NH + lh);
        ce1 = __ldg(el + cs1 * NH + lh);
        ce2 = __ldg(el + cs2 * NH + lh);
        ce3 = __ldg(el + cs3 * NH + lh);
    }
    while (have) {
        int   s0 = cs0, s1 = cs1, s2 = cs2, s3 = cs3;
        float e0 = ce0, e1 = ce1, e2 = ce2, e3 = ce3;
        i += 4;
        have = (i + 4 <= e);
        if (have) {   // prefetch next batch: overlaps exp + z-accumulate below
            cs0 = __ldg(src + i);     cs1 = __ldg(src + i + 1);
            cs2 = __ldg(src + i + 2); cs3 = __ldg(src + i + 3);
            ce0 = __ldg(el + cs0 * NH + lh);
            ce1 = __ldg(el + cs1 * NH + lh);
            ce2 = __ldg(el + cs2 * NH + lh);
            ce3 = __ldg(el + cs3 * NH + lh);
        }

        float v0 = e0 + er_h; v0 = v0 > 0.f ? v0 : 0.2f * v0;
        float v1 = e1 + er_h; v1 = v1 > 0.f ? v1 : 0.2f * v1;
        float v2 = e2 + er_h; v2 = v2 > 0.f ? v2 : 0.2f * v2;
        float v3 = e3 + er_h; v3 = v3 > 0.f ? v3 : 0.2f * v3;
        float w0 = __expf(v0), w1 = __expf(v1);
        float w2 = __expf(v2), w3 = __expf(v3);
        den += (w0 + w1) + (w2 + w3);

        __half2 hw0 = __float2half2_rn(w0), hw1 = __float2half2_rn(w1);
        __half2 hw2 = __float2half2_rn(w2), hw3 = __float2half2_rn(w3);
        uint32_t u0 = *(uint32_t*)&hw0, u1 = *(uint32_t*)&hw1;
        uint32_t u2 = *(uint32_t*)&hw2, u3 = *(uint32_t*)&hw3;

        __half2 hacc0[4], hacc1[4];
        {
            const uint4* z0 = zb + (size_t)s0 * 64;
            const uint4* z1 = zb + (size_t)s1 * 64;
            uint4 a0 = z0[lane], b0 = z0[32 + lane];
            uint4 a1 = z1[lane], b1 = z1[32 + lane];
            uint32_t w0a = __shfl_sync(0xffffffffu, u0, hsel);
            uint32_t w0b = __shfl_sync(0xffffffffu, u0, 4 + hsel);
            uint32_t w1a = __shfl_sync(0xffffffffu, u1, hsel);
            uint32_t w1b = __shfl_sync(0xffffffffu, u1, 4 + hsel);
            hmul4(hacc0, a0, w0a); hmul4(hacc1, b0, w0b);
            hfma4(hacc0, a1, w1a); hfma4(hacc1, b1, w1b);
        }
        {
            const uint4* z2 = zb + (size_t)s2 * 64;
            const uint4* z3 = zb + (size_t)s3 * 64;
            uint4 a2 = z2[lane], b2 = z2[32 + lane];
            uint4 a3 = z3[lane], b3 = z3[32 + lane];
            uint32_t w2a = __shfl_sync(0xffffffffu, u2, hsel);
            uint32_t w2b = __shfl_sync(0xffffffffu, u2, 4 + hsel);
            uint32_t w3a = __shfl_sync(0xffffffffu, u3, hsel);
            uint32_t w3b = __shfl_sync(0xffffffffu, u3, 4 + hsel);
            hfma4(hacc0, a2, w2a); hfma4(hacc1, b2, w2b);
            hfma4(hacc0, a3, w3a); hfma4(hacc1, b3, w3b);
        }
        promote4(acc[0], hacc0);
        promote4(acc[1], hacc1);
    }
    for (; i < e; i++) {
        int s0 = __ldg(src + i);
        float v0 = __ldg(el + s0 * NH + lh) + er_h;
        v0 = v0 > 0.f ? v0 : 0.2f * v0;
        float w0 = __expf(v0);
        den += w0;
        const uint4* z0 = zb + (size_t)s0 * 64;
        uint4 a0 = z0[lane], b0 = z0[32 + lane];
        float w0c0 = __shfl_sync(0xffffffffu, w0, hsel);
        float w0c1 = __shfl_sync(0xffffffffu, w0, 4 + hsel);
        acc8(acc[0], a0, w0c0); acc8(acc[1], b0, w0c1);
    }

#pragma unroll
    for (int j = 0; j < 2; j++) {
        float dk  = __shfl_sync(0xffffffffu, den, 4 * j + hsel);
        float inv = 1.f / dk;
        float o[8];
#pragma unroll
        for (int t = 0; t < 8; t++) {
            float v = acc[j][t] * inv;
            o[t] = v > 0.f ? v : (__expf(v) - 1.f);
        }
        __half2 p[4];
#pragma unroll
        for (int t = 0; t < 4; t++)
            p[t] = __floats2half2_rn(o[2 * t], o[2 * t + 1]);
        *(uint4*)(xout + (size_t)n * D1 + j * 256 + 8 * lane) = *(uint4*)p;
    }
}

// F=32, H=1: warp per node, 8 nodes per block, fp32 z, no ELU.
__global__ void gat_edge32(const int* __restrict__ src,
                           const int* __restrict__ offs,
                           const float* __restrict__ el,
                           const float* __restrict__ er,
                           const float* __restrict__ z,
                           float* __restrict__ out, int N) {
    const int n    = blockIdx.x * 8 + (threadIdx.x >> 5);
    const int lane = threadIdx.x & 31;
    if (n >= N) return;
    const int s = offs[n], e = offs[n + 1];

    float* op = out + (size_t)n * 32 + lane;
    if (s == e) { *op = 0.f; return; }

    const float er_n = er[n];
    float acc = 0.f, den = 0.f;
    int i = s;
    for (; i + 4 <= e; i += 4) {
        int s0 = __ldg(src + i),     s1 = __ldg(src + i + 1);
        int s2 = __ldg(src + i + 2), s3 = __ldg(src + i + 3);
        float e0 = __ldg(el + s0), e1 = __ldg(el + s1);
        float e2 = __ldg(el + s2), e3 = __ldg(el + s3);
        float v0 = e0 + er_n; v0 = v0 > 0.f ? v0 : 0.2f * v0;
        float v1 = e1 + er_n; v1 = v1 > 0.f ? v1 : 0.2f * v1;
        float v2 = e2 + er_n; v2 = v2 > 0.f ? v2 : 0.2f * v2;
        float v3 = e3 + er_n; v3 = v3 > 0.f ? v3 : 0.2f * v3;
        float w0 = __expf(v0), w1 = __expf(v1);
        float w2 = __expf(v2), w3 = __expf(v3);
        float z0 = z[(size_t)s0 * 32 + lane];
        float z1 = z[(size_t)s1 * 32 + lane];
        float z2 = z[(size_t)s2 * 32 + lane];
        float z3 = z[(size_t)s3 * 32 + lane];
        den += (w0 + w1) + (w2 + w3);
        acc = fmaf(w0, z0, fmaf(w1, z1, fmaf(w2, z2, fmaf(w3, z3, acc))));
    }
    for (; i < e; i++) {
        int s0 = __ldg(src + i);
        float v0 = __ldg(el + s0) + er_n; v0 = v0 > 0.f ? v0 : 0.2f * v0;
        float w0 = __expf(v0);
        den += w0;
        acc = fmaf(w0, z[(size_t)s0 * 32 + lane], acc);
    }
    *op = acc / den;
}

// ---------------------------------------------------------------------------
extern "C" void kernel_launch(void* const* d_in, const int* in_sizes, int n_in,
                              void* d_out, int out_size) {
    const float* h   = (const float*)d_in[0];
    const int*   src = (const int*)  d_in[1];
    const int*   dst = (const int*)  d_in[2];
    const float* W1  = (const float*)d_in[3];
    const float* al1 = (const float*)d_in[4];
    const float* ar1 = (const float*)d_in[5];
    const float* W2  = (const float*)d_in[6];
    const float* al2 = (const float*)d_in[7];
    const float* ar2 = (const float*)d_in[8];
    const float* W3  = (const float*)d_in[9];
    const float* al3 = (const float*)d_in[10];
    const float* ar3 = (const float*)d_in[11];
    float* out = (float*)d_out;

    __half *h16, *w1, *w2, *w3, *z16, *x16;
    float *z3, *el, *er; int* offs;
    cudaGetSymbolAddress((void**)&h16,  g_h16);
    cudaGetSymbolAddress((void**)&w1,   g_w1);
    cudaGetSymbolAddress((void**)&w2,   g_w2);
    cudaGetSymbolAddress((void**)&w3,   g_w3);
    cudaGetSymbolAddress((void**)&z16,  g_z16);
    cudaGetSymbolAddress((void**)&x16,  g_x16);
    cudaGetSymbolAddress((void**)&z3,   g_z3);
    cudaGetSymbolAddress((void**)&el,   g_el);
    cudaGetSymbolAddress((void**)&er,   g_er);
    cudaGetSymbolAddress((void**)&offs, g_offs);

    cudaFuncSetAttribute(gemm_nt_f16<1>,
                         cudaFuncAttributeMaxDynamicSharedMemorySize, GEMM16_SMEM);
    cudaFuncSetAttribute(gemm_nt_f16<2>,
                         cudaFuncAttributeMaxDynamicSharedMemorySize, GEMM16_SMEM);

    const int N = NN;

    convert_all<<<2048, 256>>>(h, W1, W2, W3, h16, w1, w2, w3);
    build_offsets<<<(N + 1 + 255) / 256, 256>>>(dst, NE, N, offs);

    dim3 g12(D1 / 64, (N + 127) / 128);   // (8, 196)
    dim3 g3(1, (N + 127) / 128);
    const int eb = (N + 7) / 8;

    // ---- layer 1 ----
    gemm_nt_f16<1><<<g12, 256, GEMM16_SMEM>>>(h16, w1, z16, nullptr,
                                              al1, ar1, el, er, N, D1, DIN);
    gat_edge_all<<<eb, 256>>>(src, offs, el, er, z16, x16, N);

    // ---- layer 2 ----
    gemm_nt_f16<1><<<g12, 256, GEMM16_SMEM>>>(x16, w2, z16, nullptr,
                                              al2, ar2, el, er, N, D1, D1);
    gat_edge_all<<<eb, 256>>>(src, offs, el, er, z16, x16, N);

    // ---- layer 3 (H=1, F=32, no ELU, fp32 out; attn fused in epilogue) ----
    gemm_nt_f16<2><<<g3, 256, GEMM16_SMEM>>>(x16, w3, nullptr, z3,
                                             al3, ar3, el, er, N, NCLS, D1);
    gat_edge32<<<eb, 256>>>(src, offs, el, er, z3, out, N);
}

// round 15
// speedup vs baseline: 1.0787x; 1.0787x over previous
#include <cuda_runtime.h>
#include <cuda_fp16.h>
#include <math.h>
#include <stdint.h>

#define NN 25000
#define NE 400000
#define DIN 256
#define HID 64
#define NH 8
#define NCLS 32
#define D1 (HID*NH)   // 512

// Scratch (device globals; no allocation allowed)
__device__ __half g_h16[NN * DIN];
__device__ __half g_w1 [D1 * DIN];
__device__ __half g_w2 [D1 * D1];
__device__ __half g_w3 [NCLS * D1];
__device__ __half g_z16[NN * D1];
__device__ __half g_x16[NN * D1];
__device__ float  g_z3 [NN * NCLS];
__device__ float  g_el [NN * NH];
__device__ float  g_er [NN * NH];
__device__ int    g_offs[NN + 1];

// ---------------------------------------------------------------------------
// Single setup launch: fp32->fp16 conversions (h, W1, W2, W3) + CSR offsets.
// ---------------------------------------------------------------------------
__global__ void setup_all(const float* __restrict__ h,  const float* __restrict__ W1,
                          const float* __restrict__ W2, const float* __restrict__ W3,
                          __half* __restrict__ h16, __half* __restrict__ w1,
                          __half* __restrict__ w2,  __half* __restrict__ w3,
                          const int* __restrict__ dst, int* __restrict__ offs) {
    const int n0 = NN * DIN / 2, n1 = D1 * DIN / 2, n2 = D1 * D1 / 2, n3 = NCLS * D1 / 2;
    const int conv_total = n0 + n1 + n2 + n3;
    const int total = conv_total + NN + 1;
    int i = blockIdx.x * blockDim.x + threadIdx.x;
    int stride = gridDim.x * blockDim.x;
    for (; i < total; i += stride) {
        if (i < conv_total) {
            const float2* s; __half2* d; int j;
            if (i < n0)                { s = (const float2*)h;  d = (__half2*)h16; j = i; }
            else if (i < n0 + n1)      { s = (const float2*)W1; d = (__half2*)w1;  j = i - n0; }
            else if (i < n0 + n1 + n2) { s = (const float2*)W2; d = (__half2*)w2;  j = i - n0 - n1; }
            else                       { s = (const float2*)W3; d = (__half2*)w3;  j = i - n0 - n1 - n2; }
            float2 v = s[j];
            d[j] = __floats2half2_rn(v.x, v.y);
        } else {
            int n = i - conv_total;      // 0..NN
            int lo = 0, hi = NE;
            while (lo < hi) {
                int mid = (lo + hi) >> 1;
                if (dst[mid] < n) lo = mid + 1; else hi = mid;
            }
            offs[n] = lo;
        }
    }
}

// ---------------------------------------------------------------------------
// FP16 tensor-core NT GEMM (R10 proven): 128x64x64 tile, 8 warps (4m x 2n),
// warp tile 32x32, mma.m16n8k16, ldmatrix frag loads, 2-stage cp.async.
// MODE 1: fp16 C16 + fused per-head el/er. MODE 2: fp32 C32 + fused attn (L3).
// ---------------------------------------------------------------------------
__device__ __forceinline__ void cpasync16h(uint32_t smem, const __half* g, bool pred) {
    int sz = pred ? 16 : 0;
    asm volatile("cp.async.cg.shared.global [%0], [%1], 16, %2;\n"
                 :: "r"(smem), "l"(g), "r"(sz));
}

__device__ __forceinline__ void ldsm_x4(uint32_t& r0, uint32_t& r1,
                                        uint32_t& r2, uint32_t& r3, uint32_t addr) {
    asm volatile("ldmatrix.sync.aligned.m8n8.x4.shared.b16 {%0,%1,%2,%3}, [%4];"
                 : "=r"(r0), "=r"(r1), "=r"(r2), "=r"(r3) : "r"(addr));
}

#define GEMM16_SMEM ((2*128*72 + 2*64*72) * 2)   // 55296 bytes

template <int MODE>
__global__ void __launch_bounds__(256)
gemm_nt_f16(const __half* __restrict__ A, const __half* __restrict__ B,
            __half* __restrict__ C16, float* __restrict__ C32,
            const float* __restrict__ al, const float* __restrict__ ar,
            float* __restrict__ el, float* __restrict__ er,
            int M, int N, int K) {
    extern __shared__ __half sm16[];
    __half* As = sm16;                 // [2][128*72]
    __half* Bs = sm16 + 2 * 128 * 72;  // [2][64*72]
    __shared__ float sred[4][128];

    const int tid  = threadIdx.x;
    const int lane = tid & 31;
    const int wid  = tid >> 5;
    const int wm   = wid & 3;
    const int wn   = wid >> 2;
    const int m0   = blockIdx.y * 128;
    const int n0   = blockIdx.x * 64;
    const int g    = lane >> 2;
    const int tg   = lane & 3;

    const uint32_t sA = (uint32_t)__cvta_generic_to_shared(As);
    const uint32_t sB = (uint32_t)__cvta_generic_to_shared(Bs);

    const int aoff0 = (wm * 32 + (lane & 15)) * 72 + ((lane >> 4) << 3);
    const int boff0 = (wn * 32 + (lane & 7) + ((lane >> 4) << 3)) * 72 + (((lane >> 3) & 1) << 3);

    float c[2][4][4];
#pragma unroll
    for (int im = 0; im < 2; im++)
#pragma unroll
        for (int in = 0; in < 4; in++)
#pragma unroll
            for (int k = 0; k < 4; k++) c[im][in][k] = 0.f;

    const int rA = tid >> 3;
    const int kq = (tid & 7) * 8;

    auto load_tile = [&](int buf, int k0) {
#pragma unroll
        for (int it = 0; it < 4; it++) {
            int r  = rA + it * 32;
            int gm = m0 + r;
            cpasync16h(sA + (uint32_t)(buf * 128 * 72 + r * 72 + kq) * 2,
                       A + (size_t)gm * K + k0 + kq, gm < M);
        }
#pragma unroll
        for (int it = 0; it < 2; it++) {
            int r  = rA + it * 32;
            int gn = n0 + r;
            cpasync16h(sB + (uint32_t)(buf * 64 * 72 + r * 72 + kq) * 2,
                       B + (size_t)gn * K + k0 + kq, gn < N);
        }
        asm volatile("cp.async.commit_group;\n");
    };

    const int T = K >> 6;
    load_tile(0, 0);

    for (int t = 0; t < T; t++) {
        const int buf = t & 1;
        if (t + 1 < T) {
            load_tile(buf ^ 1, (t + 1) << 6);
            asm volatile("cp.async.wait_group 1;\n");
        } else {
            asm volatile("cp.async.wait_group 0;\n");
        }
        __syncthreads();

        const uint32_t aBase = sA + (uint32_t)(buf * 128 * 72 + aoff0) * 2;
        const uint32_t bBase = sB + (uint32_t)(buf * 64 * 72 + boff0) * 2;
#pragma unroll
        for (int kk = 0; kk < 64; kk += 16) {
            uint32_t a[2][4];
#pragma unroll
            for (int im = 0; im < 2; im++)
                ldsm_x4(a[im][0], a[im][1], a[im][2], a[im][3],
                        aBase + (uint32_t)(im * 16 * 72 + kk) * 2);
            uint32_t b[4][2];
#pragma unroll
            for (int p = 0; p < 2; p++)
                ldsm_x4(b[2 * p][0], b[2 * p][1], b[2 * p + 1][0], b[2 * p + 1][1],
                        bBase + (uint32_t)(p * 16 * 72 + kk) * 2);
#pragma unroll
            for (int im = 0; im < 2; im++)
#pragma unroll
                for (int in = 0; in < 4; in++) {
                    asm volatile(
                        "mma.sync.aligned.m16n8k16.row.col.f32.f16.f16.f32 "
                        "{%0,%1,%2,%3}, {%4,%5,%6,%7}, {%8,%9}, {%0,%1,%2,%3};\n"
                        : "+f"(c[im][in][0]), "+f"(c[im][in][1]),
                          "+f"(c[im][in][2]), "+f"(c[im][in][3])
                        : "r"(a[im][0]), "r"(a[im][1]), "r"(a[im][2]), "r"(a[im][3]),
                          "r"(b[in][0]), "r"(b[in][1]));
                }
        }
        __syncthreads();
    }

    // ---- store C ----
#pragma unroll
    for (int im = 0; im < 2; im++) {
        int r0 = m0 + wm * 32 + im * 16 + g;
#pragma unroll
        for (int in = 0; in < 4; in++) {
            int gn = n0 + wn * 32 + in * 8 + 2 * tg;
            if (gn >= N) continue;
            if (MODE == 1) {
                if (r0 < M)
                    *(__half2*)(C16 + (size_t)r0 * N + gn) =
                        __floats2half2_rn(c[im][in][0], c[im][in][1]);
                if (r0 + 8 < M)
                    *(__half2*)(C16 + (size_t)(r0 + 8) * N + gn) =
                        __floats2half2_rn(c[im][in][2], c[im][in][3]);
            } else {
                if (r0 < M)
                    *(float2*)(C32 + (size_t)r0 * N + gn) =
                        make_float2(c[im][in][0], c[im][in][1]);
                if (r0 + 8 < M)
                    *(float2*)(C32 + (size_t)(r0 + 8) * N + gn) =
                        make_float2(c[im][in][2], c[im][in][3]);
            }
        }
    }

    // ---- fused el/er ----
    {
        const int F = (MODE == 1) ? HID : NCLS;
        const int h = (MODE == 1) ? blockIdx.x : 0;
        float elp[2][2], erp[2][2];
#pragma unroll
        for (int im = 0; im < 2; im++) {
            elp[im][0] = elp[im][1] = 0.f;
            erp[im][0] = erp[im][1] = 0.f;
        }
#pragma unroll
        for (int in = 0; in < 4; in++) {
            int cf = wn * 32 + in * 8 + 2 * tg;
            float a0 = 0.f, a1 = 0.f, b0 = 0.f, b1 = 0.f;
            if (cf < F) {
                a0 = al[h * F + cf]; a1 = al[h * F + cf + 1];
                b0 = ar[h * F + cf]; b1 = ar[h * F + cf + 1];
            }
#pragma unroll
            for (int im = 0; im < 2; im++) {
                elp[im][0] = fmaf(c[im][in][0], a0, fmaf(c[im][in][1], a1, elp[im][0]));
                elp[im][1] = fmaf(c[im][in][2], a0, fmaf(c[im][in][3], a1, elp[im][1]));
                erp[im][0] = fmaf(c[im][in][0], b0, fmaf(c[im][in][1], b1, erp[im][0]));
                erp[im][1] = fmaf(c[im][in][2], b0, fmaf(c[im][in][3], b1, erp[im][1]));
            }
        }
#pragma unroll
        for (int o = 1; o <= 2; o <<= 1) {
#pragma unroll
            for (int im = 0; im < 2; im++) {
#pragma unroll
                for (int r = 0; r < 2; r++) {
                    elp[im][r] += __shfl_xor_sync(0xffffffffu, elp[im][r], o);
                    erp[im][r] += __shfl_xor_sync(0xffffffffu, erp[im][r], o);
                }
            }
        }
        if (tg == 0) {
#pragma unroll
            for (int im = 0; im < 2; im++) {
#pragma unroll
                for (int r = 0; r < 2; r++) {
                    int row = wm * 32 + im * 16 + r * 8 + g;
                    sred[wn][row]     = elp[im][r];
                    sred[2 + wn][row] = erp[im][r];
                }
            }
        }
        __syncthreads();
        if (tid < 128) {
            int gm = m0 + tid;
            if (gm < M) {
                float ev = sred[0][tid] + sred[1][tid];
                float rv = sred[2][tid] + sred[3][tid];
                if (MODE == 1) { el[gm * NH + h] = ev; er[gm * NH + h] = rv; }
                else           { el[gm] = ev;          er[gm] = rv; }
            }
        }
    }
}

// ---------------------------------------------------------------------------
// Edge softmax + aggregation over fp16 z (R10 proven body), but only
// 2 NODES PER 64-THREAD BLOCK to minimize intra-block load imbalance
// (node degree varies; small blocks let the SM scheduler backfill).
// ---------------------------------------------------------------------------
__device__ __forceinline__ void acc8(float* acc, uint4 q, float w) {
    const __half2* hp = (const __half2*)&q;
#pragma unroll
    for (int t = 0; t < 4; t++) {
        float2 f = __half22float2(hp[t]);
        acc[2 * t]     = fmaf(w, f.x, acc[2 * t]);
        acc[2 * t + 1] = fmaf(w, f.y, acc[2 * t + 1]);
    }
}
__device__ __forceinline__ void hmul4(__half2* hacc, uint4 q, uint32_t wu) {
    __half2 w2 = *(__half2*)&wu;
    const __half2* hp = (const __half2*)&q;
#pragma unroll
    for (int t = 0; t < 4; t++) hacc[t] = __hmul2(w2, hp[t]);
}
__device__ __forceinline__ void hfma4(__half2* hacc, uint4 q, uint32_t wu) {
    __half2 w2 = *(__half2*)&wu;
    const __half2* hp = (const __half2*)&q;
#pragma unroll
    for (int t = 0; t < 4; t++) hacc[t] = __hfma2(w2, hp[t], hacc[t]);
}
__device__ __forceinline__ void promote4(float* acc, const __half2* hacc) {
#pragma unroll
    for (int t = 0; t < 4; t++) {
        float2 f = __half22float2(hacc[t]);
        acc[2 * t]     += f.x;
        acc[2 * t + 1] += f.y;
    }
}

__global__ void __launch_bounds__(64)
gat_edge_all(const int* __restrict__ src, const int* __restrict__ offs,
             const float* __restrict__ el, const float* __restrict__ er,
             const __half* __restrict__ z16, __half* __restrict__ xout, int N) {
    const int n    = blockIdx.x * 2 + (threadIdx.x >> 5);
    const int lane = threadIdx.x & 31;
    if (n >= N) return;
    const int s = offs[n], e = offs[n + 1];

    if (s == e) {
        uint4 zq = make_uint4(0, 0, 0, 0);
#pragma unroll
        for (int j = 0; j < 2; j++)
            *(uint4*)(xout + (size_t)n * D1 + j * 256 + 8 * lane) = zq;
        return;
    }

    const float er_h = (lane < 8) ? er[n * NH + lane] : 0.f;
    const int   lh   = lane & 7;
    const int   hsel = lane >> 3;
    const uint4* zb  = (const uint4*)z16;

    float acc[2][8];
#pragma unroll
    for (int j = 0; j < 2; j++)
#pragma unroll
        for (int t = 0; t < 8; t++) acc[j][t] = 0.f;
    float den = 0.f;

    int i = s;
    for (; i + 4 <= e; i += 4) {
        int s0 = __ldg(src + i),     s1 = __ldg(src + i + 1);
        int s2 = __ldg(src + i + 2), s3 = __ldg(src + i + 3);
        float e0 = __ldg(el + s0 * NH + lh);
        float e1 = __ldg(el + s1 * NH + lh);
        float e2 = __ldg(el + s2 * NH + lh);
        float e3 = __ldg(el + s3 * NH + lh);
        float v0 = e0 + er_h; v0 = v0 > 0.f ? v0 : 0.2f * v0;
        float v1 = e1 + er_h; v1 = v1 > 0.f ? v1 : 0.2f * v1;
        float v2 = e2 + er_h; v2 = v2 > 0.f ? v2 : 0.2f * v2;
        float v3 = e3 + er_h; v3 = v3 > 0.f ? v3 : 0.2f * v3;
        float w0 = __expf(v0), w1 = __expf(v1);
        float w2 = __expf(v2), w3 = __expf(v3);
        den += (w0 + w1) + (w2 + w3);

        __half2 hw0 = __float2half2_rn(w0), hw1 = __float2half2_rn(w1);
        __half2 hw2 = __float2half2_rn(w2), hw3 = __float2half2_rn(w3);
        uint32_t u0 = *(uint32_t*)&hw0, u1 = *(uint32_t*)&hw1;
        uint32_t u2 = *(uint32_t*)&hw2, u3 = *(uint32_t*)&hw3;

        __half2 hacc0[4], hacc1[4];
        {
            const uint4* z0 = zb + (size_t)s0 * 64;
            const uint4* z1 = zb + (size_t)s1 * 64;
            uint4 a0 = z0[lane], b0 = z0[32 + lane];
            uint4 a1 = z1[lane], b1 = z1[32 + lane];
            uint32_t w0a = __shfl_sync(0xffffffffu, u0, hsel);
            uint32_t w0b = __shfl_sync(0xffffffffu, u0, 4 + hsel);
            uint32_t w1a = __shfl_sync(0xffffffffu, u1, hsel);
            uint32_t w1b = __shfl_sync(0xffffffffu, u1, 4 + hsel);
            hmul4(hacc0, a0, w0a); hmul4(hacc1, b0, w0b);
            hfma4(hacc0, a1, w1a); hfma4(hacc1, b1, w1b);
        }
        {
            const uint4* z2 = zb + (size_t)s2 * 64;
            const uint4* z3 = zb + (size_t)s3 * 64;
            uint4 a2 = z2[lane], b2 = z2[32 + lane];
            uint4 a3 = z3[lane], b3 = z3[32 + lane];
            uint32_t w2a = __shfl_sync(0xffffffffu, u2, hsel);
            uint32_t w2b = __shfl_sync(0xffffffffu, u2, 4 + hsel);
            uint32_t w3a = __shfl_sync(0xffffffffu, u3, hsel);
            uint32_t w3b = __shfl_sync(0xffffffffu, u3, 4 + hsel);
            hfma4(hacc0, a2, w2a); hfma4(hacc1, b2, w2b);
            hfma4(hacc0, a3, w3a); hfma4(hacc1, b3, w3b);
        }
        promote4(acc[0], hacc0);
        promote4(acc[1], hacc1);
    }
    for (; i < e; i++) {
        int s0 = __ldg(src + i);
        float v0 = __ldg(el + s0 * NH + lh) + er_h;
        v0 = v0 > 0.f ? v0 : 0.2f * v0;
        float w0 = __expf(v0);
        den += w0;
        const uint4* z0 = zb + (size_t)s0 * 64;
        uint4 a0 = z0[lane], b0 = z0[32 + lane];
        float w0c0 = __shfl_sync(0xffffffffu, w0, hsel);
        float w0c1 = __shfl_sync(0xffffffffu, w0, 4 + hsel);
        acc8(acc[0], a0, w0c0); acc8(acc[1], b0, w0c1);
    }

#pragma unroll
    for (int j = 0; j < 2; j++) {
        float dk  = __shfl_sync(0xffffffffu, den, 4 * j + hsel);
        float inv = 1.f / dk;
        float o[8];
#pragma unroll
        for (int t = 0; t < 8; t++) {
            float v = acc[j][t] * inv;
            o[t] = v > 0.f ? v : (__expf(v) - 1.f);
        }
        __half2 p[4];
#pragma unroll
        for (int t = 0; t < 4; t++)
            p[t] = __floats2half2_rn(o[2 * t], o[2 * t + 1]);
        *(uint4*)(xout + (size_t)n * D1 + j * 256 + 8 * lane) = *(uint4*)p;
    }
}

// F=32, H=1: warp per node, 2 nodes per 64-thread block, fp32 z, no ELU.
__global__ void __launch_bounds__(64)
gat_edge32(const int* __restrict__ src,
           const int* __restrict__ offs,
           const float* __restrict__ el,
           const float* __restrict__ er,
           const float* __restrict__ z,
           float* __restrict__ out, int N) {
    const int n    = blockIdx.x * 2 + (threadIdx.x >> 5);
    const int lane = threadIdx.x & 31;
    if (n >= N) return;
    const int s = offs[n], e = offs[n + 1];

    float* op = out + (size_t)n * 32 + lane;
    if (s == e) { *op = 0.f; return; }

    const float er_n = er[n];
    float acc = 0.f, den = 0.f;
    int i = s;
    for (; i + 4 <= e; i += 4) {
        int s0 = __ldg(src + i),     s1 = __ldg(src + i + 1);
        int s2 = __ldg(src + i + 2), s3 = __ldg(src + i + 3);
        float e0 = __ldg(el + s0), e1 = __ldg(el + s1);
        float e2 = __ldg(el + s2), e3 = __ldg(el + s3);
        float v0 = e0 + er_n; v0 = v0 > 0.f ? v0 : 0.2f * v0;
        float v1 = e1 + er_n; v1 = v1 > 0.f ? v1 : 0.2f * v1;
        float v2 = e2 + er_n; v2 = v2 > 0.f ? v2 : 0.2f * v2;
        float v3 = e3 + er_n; v3 = v3 > 0.f ? v3 : 0.2f * v3;
        float w0 = __expf(v0), w1 = __expf(v1);
        float w2 = __expf(v2), w3 = __expf(v3);
        float z0 = z[(size_t)s0 * 32 + lane];
        float z1 = z[(size_t)s1 * 32 + lane];
        float z2 = z[(size_t)s2 * 32 + lane];
        float z3 = z[(size_t)s3 * 32 + lane];
        den += (w0 + w1) + (w2 + w3);
        acc = fmaf(w0, z0, fmaf(w1, z1, fmaf(w2, z2, fmaf(w3, z3, acc))));
    }
    for (; i < e; i++) {
        int s0 = __ldg(src + i);
        float v0 = __ldg(el + s0) + er_n; v0 = v0 > 0.f ? v0 : 0.2f * v0;
        float w0 = __expf(v0);
        den += w0;
        acc = fmaf(w0, z[(size_t)s0 * 32 + lane], acc);
    }
    *op = acc / den;
}

// ---------------------------------------------------------------------------
extern "C" void kernel_launch(void* const* d_in, const int* in_sizes, int n_in,
                              void* d_out, int out_size) {
    const float* h   = (const float*)d_in[0];
    const int*   src = (const int*)  d_in[1];
    const int*   dst = (const int*)  d_in[2];
    const float* W1  = (const float*)d_in[3];
    const float* al1 = (const float*)d_in[4];
    const float* ar1 = (const float*)d_in[5];
    const float* W2  = (const float*)d_in[6];
    const float* al2 = (const float*)d_in[7];
    const float* ar2 = (const float*)d_in[8];
    const float* W3  = (const float*)d_in[9];
    const float* al3 = (const float*)d_in[10];
    const float* ar3 = (const float*)d_in[11];
    float* out = (float*)d_out;

    __half *h16, *w1, *w2, *w3, *z16, *x16;
    float *z3, *el, *er; int* offs;
    cudaGetSymbolAddress((void**)&h16,  g_h16);
    cudaGetSymbolAddress((void**)&w1,   g_w1);
    cudaGetSymbolAddress((void**)&w2,   g_w2);
    cudaGetSymbolAddress((void**)&w3,   g_w3);
    cudaGetSymbolAddress((void**)&z16,  g_z16);
    cudaGetSymbolAddress((void**)&x16,  g_x16);
    cudaGetSymbolAddress((void**)&z3,   g_z3);
    cudaGetSymbolAddress((void**)&el,   g_el);
    cudaGetSymbolAddress((void**)&er,   g_er);
    cudaGetSymbolAddress((void**)&offs, g_offs);

    cudaFuncSetAttribute(gemm_nt_f16<1>,
                         cudaFuncAttributeMaxDynamicSharedMemorySize, GEMM16_SMEM);
    cudaFuncSetAttribute(gemm_nt_f16<2>,
                         cudaFuncAttributeMaxDynamicSharedMemorySize, GEMM16_SMEM);

    const int N = NN;

    setup_all<<<2048, 256>>>(h, W1, W2, W3, h16, w1, w2, w3, dst, offs);

    dim3 g12(D1 / 64, (N + 127) / 128);   // (8, 196)
    dim3 g3(1, (N + 127) / 128);
    const int eb = (N + 1) / 2;           // 2 nodes per 64-thread block

    // ---- layer 1 ----
    gemm_nt_f16<1><<<g12, 256, GEMM16_SMEM>>>(h16, w1, z16, nullptr,
                                              al1, ar1, el, er, N, D1, DIN);
    gat_edge_all<<<eb, 64>>>(src, offs, el, er, z16, x16, N);

    // ---- layer 2 ----
    gemm_nt_f16<1><<<g12, 256, GEMM16_SMEM>>>(x16, w2, z16, nullptr,
                                              al2, ar2, el, er, N, D1, D1);
    gat_edge_all<<<eb, 64>>>(src, offs, el, er, z16, x16, N);

    // ---- layer 3 (H=1, F=32, no ELU, fp32 out; attn fused in epilogue) ----
    gemm_nt_f16<2><<<g3, 256, GEMM16_SMEM>>>(x16, w3, nullptr, z3,
                                             al3, ar3, el, er, N, NCLS, D1);
    gat_edge32<<<eb, 64>>>(src, offs, el, er, z3, out, N);
}

// round 17
// speedup vs baseline: 1.0924x; 1.0127x over previous
#include <cuda_runtime.h>
#include <cuda_fp16.h>
#include <math.h>
#include <stdint.h>

#define NN 25000
#define NE 400000
#define DIN 256
#define HID 64
#define NH 8
#define NCLS 32
#define D1 (HID*NH)   // 512

// Scratch (device globals; no allocation allowed)
__device__ __half g_h16[NN * DIN];
__device__ __half g_w1 [D1 * DIN];
__device__ __half g_w2 [D1 * D1];
__device__ __half g_w3 [NCLS * D1];
__device__ __half g_z16[NN * D1];
__device__ __half g_x16[NN * D1];
__device__ float  g_z3 [NN * NCLS];
__device__ float  g_el [NN * NH];
__device__ float  g_er [NN * NH];
__device__ int    g_offs[NN + 1];

// ---------------------------------------------------------------------------
// Single setup launch: fp32->fp16 conversions (h, W1, W2, W3) + CSR offsets.
// ---------------------------------------------------------------------------
__global__ void setup_all(const float* __restrict__ h,  const float* __restrict__ W1,
                          const float* __restrict__ W2, const float* __restrict__ W3,
                          __half* __restrict__ h16, __half* __restrict__ w1,
                          __half* __restrict__ w2,  __half* __restrict__ w3,
                          const int* __restrict__ dst, int* __restrict__ offs) {
    const int n0 = NN * DIN / 2, n1 = D1 * DIN / 2, n2 = D1 * D1 / 2, n3 = NCLS * D1 / 2;
    const int conv_total = n0 + n1 + n2 + n3;
    const int total = conv_total + NN + 1;
    int i = blockIdx.x * blockDim.x + threadIdx.x;
    int stride = gridDim.x * blockDim.x;
    for (; i < total; i += stride) {
        if (i < conv_total) {
            const float2* s; __half2* d; int j;
            if (i < n0)                { s = (const float2*)h;  d = (__half2*)h16; j = i; }
            else if (i < n0 + n1)      { s = (const float2*)W1; d = (__half2*)w1;  j = i - n0; }
            else if (i < n0 + n1 + n2) { s = (const float2*)W2; d = (__half2*)w2;  j = i - n0 - n1; }
            else                       { s = (const float2*)W3; d = (__half2*)w3;  j = i - n0 - n1 - n2; }
            float2 v = s[j];
            d[j] = __floats2half2_rn(v.x, v.y);
        } else {
            int n = i - conv_total;
            int lo = 0, hi = NE;
            while (lo < hi) {
                int mid = (lo + hi) >> 1;
                if (dst[mid] < n) lo = mid + 1; else hi = mid;
            }
            offs[n] = lo;
        }
    }
}

// ---------------------------------------------------------------------------
// FP16 tensor-core NT GEMM: 128x64x64 tile, 8 warps (4m x 2n), warp tile
// 32x32, mma.m16n8k16, ldmatrix frag loads, 2-stage cp.async.
// __launch_bounds__(256,4): cap 64 regs -> 4 CTAs/SM (was 3, reg-limited).
// MODE 1: fp16 C16 + fused per-head el/er. MODE 2: fp32 C32 + fused attn (L3).
// ---------------------------------------------------------------------------
__device__ __forceinline__ void cpasync16h(uint32_t smem, const __half* g, bool pred) {
    int sz = pred ? 16 : 0;
    asm volatile("cp.async.cg.shared.global [%0], [%1], 16, %2;\n"
                 :: "r"(smem), "l"(g), "r"(sz));
}

__device__ __forceinline__ void ldsm_x4(uint32_t& r0, uint32_t& r1,
                                        uint32_t& r2, uint32_t& r3, uint32_t addr) {
    asm volatile("ldmatrix.sync.aligned.m8n8.x4.shared.b16 {%0,%1,%2,%3}, [%4];"
                 : "=r"(r0), "=r"(r1), "=r"(r2), "=r"(r3) : "r"(addr));
}

#define GEMM16_SMEM ((2*128*72 + 2*64*72) * 2)   // 55296 bytes

template <int MODE>
__global__ void __launch_bounds__(256, 4)
gemm_nt_f16(const __half* __restrict__ A, const __half* __restrict__ B,
            __half* __restrict__ C16, float* __restrict__ C32,
            const float* __restrict__ al, const float* __restrict__ ar,
            float* __restrict__ el, float* __restrict__ er,
            int M, int N, int K) {
    extern __shared__ __half sm16[];
    __half* As = sm16;                 // [2][128*72]
    __half* Bs = sm16 + 2 * 128 * 72;  // [2][64*72]
    __shared__ float sred[4][128];

    const int tid  = threadIdx.x;
    const int lane = tid & 31;
    const int wid  = tid >> 5;
    const int wm   = wid & 3;
    const int wn   = wid >> 2;
    const int m0   = blockIdx.y * 128;
    const int n0   = blockIdx.x * 64;
    const int g    = lane >> 2;
    const int tg   = lane & 3;

    const uint32_t sA = (uint32_t)__cvta_generic_to_shared(As);
    const uint32_t sB = (uint32_t)__cvta_generic_to_shared(Bs);

    const int aoff0 = (wm * 32 + (lane & 15)) * 72 + ((lane >> 4) << 3);
    const int boff0 = (wn * 32 + (lane & 7) + ((lane >> 4) << 3)) * 72 + (((lane >> 3) & 1) << 3);

    float c[2][4][4];
#pragma unroll
    for (int im = 0; im < 2; im++)
#pragma unroll
        for (int in = 0; in < 4; in++)
#pragma unroll
            for (int k = 0; k < 4; k++) c[im][in][k] = 0.f;

    const int rA = tid >> 3;
    const int kq = (tid & 7) * 8;

    auto load_tile = [&](int buf, int k0) {
#pragma unroll
        for (int it = 0; it < 4; it++) {
            int r  = rA + it * 32;
            int gm = m0 + r;
            cpasync16h(sA + (uint32_t)(buf * 128 * 72 + r * 72 + kq) * 2,
                       A + (size_t)gm * K + k0 + kq, gm < M);
        }
#pragma unroll
        for (int it = 0; it < 2; it++) {
            int r  = rA + it * 32;
            int gn = n0 + r;
            cpasync16h(sB + (uint32_t)(buf * 64 * 72 + r * 72 + kq) * 2,
                       B + (size_t)gn * K + k0 + kq, gn < N);
        }
        asm volatile("cp.async.commit_group;\n");
    };

    const int T = K >> 6;
    load_tile(0, 0);

    for (int t = 0; t < T; t++) {
        const int buf = t & 1;
        if (t + 1 < T) {
            load_tile(buf ^ 1, (t + 1) << 6);
            asm volatile("cp.async.wait_group 1;\n");
        } else {
            asm volatile("cp.async.wait_group 0;\n");
        }
        __syncthreads();

        const uint32_t aBase = sA + (uint32_t)(buf * 128 * 72 + aoff0) * 2;
        const uint32_t bBase = sB + (uint32_t)(buf * 64 * 72 + boff0) * 2;
#pragma unroll
        for (int kk = 0; kk < 64; kk += 16) {
            uint32_t a[2][4];
#pragma unroll
            for (int im = 0; im < 2; im++)
                ldsm_x4(a[im][0], a[im][1], a[im][2], a[im][3],
                        aBase + (uint32_t)(im * 16 * 72 + kk) * 2);
            uint32_t b[4][2];
#pragma unroll
            for (int p = 0; p < 2; p++)
                ldsm_x4(b[2 * p][0], b[2 * p][1], b[2 * p + 1][0], b[2 * p + 1][1],
                        bBase + (uint32_t)(p * 16 * 72 + kk) * 2);
#pragma unroll
            for (int im = 0; im < 2; im++)
#pragma unroll
                for (int in = 0; in < 4; in++) {
                    asm volatile(
                        "mma.sync.aligned.m16n8k16.row.col.f32.f16.f16.f32 "
                        "{%0,%1,%2,%3}, {%4,%5,%6,%7}, {%8,%9}, {%0,%1,%2,%3};\n"
                        : "+f"(c[im][in][0]), "+f"(c[im][in][1]),
                          "+f"(c[im][in][2]), "+f"(c[im][in][3])
                        : "r"(a[im][0]), "r"(a[im][1]), "r"(a[im][2]), "r"(a[im][3]),
                          "r"(b[in][0]), "r"(b[in][1]));
                }
        }
        __syncthreads();
    }

    // ---- store C ----
#pragma unroll
    for (int im = 0; im < 2; im++) {
        int r0 = m0 + wm * 32 + im * 16 + g;
#pragma unroll
        for (int in = 0; in < 4; in++) {
            int gn = n0 + wn * 32 + in * 8 + 2 * tg;
            if (gn >= N) continue;
            if (MODE == 1) {
                if (r0 < M)
                    *(__half2*)(C16 + (size_t)r0 * N + gn) =
                        __floats2half2_rn(c[im][in][0], c[im][in][1]);
                if (r0 + 8 < M)
                    *(__half2*)(C16 + (size_t)(r0 + 8) * N + gn) =
                        __floats2half2_rn(c[im][in][2], c[im][in][3]);
            } else {
                if (r0 < M)
                    *(float2*)(C32 + (size_t)r0 * N + gn) =
                        make_float2(c[im][in][0], c[im][in][1]);
                if (r0 + 8 < M)
                    *(float2*)(C32 + (size_t)(r0 + 8) * N + gn) =
                        make_float2(c[im][in][2], c[im][in][3]);
            }
        }
    }

    // ---- fused el/er ----
    {
        const int F = (MODE == 1) ? HID : NCLS;
        const int h = (MODE == 1) ? blockIdx.x : 0;
        float elp[2][2], erp[2][2];
#pragma unroll
        for (int im = 0; im < 2; im++) {
            elp[im][0] = elp[im][1] = 0.f;
            erp[im][0] = erp[im][1] = 0.f;
        }
#pragma unroll
        for (int in = 0; in < 4; in++) {
            int cf = wn * 32 + in * 8 + 2 * tg;
            float a0 = 0.f, a1 = 0.f, b0 = 0.f, b1 = 0.f;
            if (cf < F) {
                a0 = al[h * F + cf]; a1 = al[h * F + cf + 1];
                b0 = ar[h * F + cf]; b1 = ar[h * F + cf + 1];
            }
#pragma unroll
            for (int im = 0; im < 2; im++) {
                elp[im][0] = fmaf(c[im][in][0], a0, fmaf(c[im][in][1], a1, elp[im][0]));
                elp[im][1] = fmaf(c[im][in][2], a0, fmaf(c[im][in][3], a1, elp[im][1]));
                erp[im][0] = fmaf(c[im][in][0], b0, fmaf(c[im][in][1], b1, erp[im][0]));
                erp[im][1] = fmaf(c[im][in][2], b0, fmaf(c[im][in][3], b1, erp[im][1]));
            }
        }
#pragma unroll
        for (int o = 1; o <= 2; o <<= 1) {
#pragma unroll
            for (int im = 0; im < 2; im++) {
#pragma unroll
                for (int r = 0; r < 2; r++) {
                    elp[im][r] += __shfl_xor_sync(0xffffffffu, elp[im][r], o);
                    erp[im][r] += __shfl_xor_sync(0xffffffffu, erp[im][r], o);
                }
            }
        }
        if (tg == 0) {
#pragma unroll
            for (int im = 0; im < 2; im++) {
#pragma unroll
                for (int r = 0; r < 2; r++) {
                    int row = wm * 32 + im * 16 + r * 8 + g;
                    sred[wn][row]     = elp[im][r];
                    sred[2 + wn][row] = erp[im][r];
                }
            }
        }
        __syncthreads();
        if (tid < 128) {
            int gm = m0 + tid;
            if (gm < M) {
                float ev = sred[0][tid] + sred[1][tid];
                float rv = sred[2][tid] + sred[3][tid];
                if (MODE == 1) { el[gm * NH + h] = ev; er[gm * NH + h] = rv; }
                else           { el[gm] = ev;          er[gm] = rv; }
            }
        }
    }
}

// ---------------------------------------------------------------------------
// Edge softmax + aggregation over fp16 z (R15 proven: 2 nodes / 64-thr block).
// ---------------------------------------------------------------------------
__device__ __forceinline__ void acc8(float* acc, uint4 q, float w) {
    const __half2* hp = (const __half2*)&q;
#pragma unroll
    for (int t = 0; t < 4; t++) {
        float2 f = __half22float2(hp[t]);
        acc[2 * t]     = fmaf(w, f.x, acc[2 * t]);
        acc[2 * t + 1] = fmaf(w, f.y, acc[2 * t + 1]);
    }
}
__device__ __forceinline__ void hmul4(__half2* hacc, uint4 q, uint32_t wu) {
    __half2 w2 = *(__half2*)&wu;
    const __half2* hp = (const __half2*)&q;
#pragma unroll
    for (int t = 0; t < 4; t++) hacc[t] = __hmul2(w2, hp[t]);
}
__device__ __forceinline__ void hfma4(__half2* hacc, uint4 q, uint32_t wu) {
    __half2 w2 = *(__half2*)&wu;
    const __half2* hp = (const __half2*)&q;
#pragma unroll
    for (int t = 0; t < 4; t++) hacc[t] = __hfma2(w2, hp[t], hacc[t]);
}
__device__ __forceinline__ void promote4(float* acc, const __half2* hacc) {
#pragma unroll
    for (int t = 0; t < 4; t++) {
        float2 f = __half22float2(hacc[t]);
        acc[2 * t]     += f.x;
        acc[2 * t + 1] += f.y;
    }
}

__global__ void __launch_bounds__(64)
gat_edge_all(const int* __restrict__ src, const int* __restrict__ offs,
             const float* __restrict__ el, const float* __restrict__ er,
             const __half* __restrict__ z16, __half* __restrict__ xout, int N) {
    const int n    = blockIdx.x * 2 + (threadIdx.x >> 5);
    const int lane = threadIdx.x & 31;
    if (n >= N) return;
    const int s = offs[n], e = offs[n + 1];

    if (s == e) {
        uint4 zq = make_uint4(0, 0, 0, 0);
#pragma unroll
        for (int j = 0; j < 2; j++)
            *(uint4*)(xout + (size_t)n * D1 + j * 256 + 8 * lane) = zq;
        return;
    }

    const float er_h = (lane < 8) ? er[n * NH + lane] : 0.f;
    const int   lh   = lane & 7;
    const int   hsel = lane >> 3;
    const uint4* zb  = (const uint4*)z16;

    float acc[2][8];
#pragma unroll
    for (int j = 0; j < 2; j++)
#pragma unroll
        for (int t = 0; t < 8; t++) acc[j][t] = 0.f;
    float den = 0.f;

    int i = s;
    for (; i + 4 <= e; i += 4) {
        int s0 = __ldg(src + i),     s1 = __ldg(src + i + 1);
        int s2 = __ldg(src + i + 2), s3 = __ldg(src + i + 3);
        float e0 = __ldg(el + s0 * NH + lh);
        float e1 = __ldg(el + s1 * NH + lh);
        float e2 = __ldg(el + s2 * NH + lh);
        float e3 = __ldg(el + s3 * NH + lh);
        float v0 = e0 + er_h; v0 = v0 > 0.f ? v0 : 0.2f * v0;
        float v1 = e1 + er_h; v1 = v1 > 0.f ? v1 : 0.2f * v1;
        float v2 = e2 + er_h; v2 = v2 > 0.f ? v2 : 0.2f * v2;
        float v3 = e3 + er_h; v3 = v3 > 0.f ? v3 : 0.2f * v3;
        float w0 = __expf(v0), w1 = __expf(v1);
        float w2 = __expf(v2), w3 = __expf(v3);
        den += (w0 + w1) + (w2 + w3);

        __half2 hw0 = __float2half2_rn(w0), hw1 = __float2half2_rn(w1);
        __half2 hw2 = __float2half2_rn(w2), hw3 = __float2half2_rn(w3);
        uint32_t u0 = *(uint32_t*)&hw0, u1 = *(uint32_t*)&hw1;
        uint32_t u2 = *(uint32_t*)&hw2, u3 = *(uint32_t*)&hw3;

        __half2 hacc0[4], hacc1[4];
        {
            const uint4* z0 = zb + (size_t)s0 * 64;
            const uint4* z1 = zb + (size_t)s1 * 64;
            uint4 a0 = z0[lane], b0 = z0[32 + lane];
            uint4 a1 = z1[lane], b1 = z1[32 + lane];
            uint32_t w0a = __shfl_sync(0xffffffffu, u0, hsel);
            uint32_t w0b = __shfl_sync(0xffffffffu, u0, 4 + hsel);
            uint32_t w1a = __shfl_sync(0xffffffffu, u1, hsel);
            uint32_t w1b = __shfl_sync(0xffffffffu, u1, 4 + hsel);
            hmul4(hacc0, a0, w0a); hmul4(hacc1, b0, w0b);
            hfma4(hacc0, a1, w1a); hfma4(hacc1, b1, w1b);
        }
        {
            const uint4* z2 = zb + (size_t)s2 * 64;
            const uint4* z3 = zb + (size_t)s3 * 64;
            uint4 a2 = z2[lane], b2 = z2[32 + lane];
            uint4 a3 = z3[lane], b3 = z3[32 + lane];
            uint32_t w2a = __shfl_sync(0xffffffffu, u2, hsel);
            uint32_t w2b = __shfl_sync(0xffffffffu, u2, 4 + hsel);
            uint32_t w3a = __shfl_sync(0xffffffffu, u3, hsel);
            uint32_t w3b = __shfl_sync(0xffffffffu, u3, 4 + hsel);
            hfma4(hacc0, a2, w2a); hfma4(hacc1, b2, w2b);
            hfma4(hacc0, a3, w3a); hfma4(hacc1, b3, w3b);
        }
        promote4(acc[0], hacc0);
        promote4(acc[1], hacc1);
    }
    for (; i < e; i++) {
        int s0 = __ldg(src + i);
        float v0 = __ldg(el + s0 * NH + lh) + er_h;
        v0 = v0 > 0.f ? v0 : 0.2f * v0;
        float w0 = __expf(v0);
        den += w0;
        const uint4* z0 = zb + (size_t)s0 * 64;
        uint4 a0 = z0[lane], b0 = z0[32 + lane];
        float w0c0 = __shfl_sync(0xffffffffu, w0, hsel);
        float w0c1 = __shfl_sync(0xffffffffu, w0, 4 + hsel);
        acc8(acc[0], a0, w0c0); acc8(acc[1], b0, w0c1);
    }

#pragma unroll
    for (int j = 0; j < 2; j++) {
        float dk  = __shfl_sync(0xffffffffu, den, 4 * j + hsel);
        float inv = 1.f / dk;
        float o[8];
#pragma unroll
        for (int t = 0; t < 8; t++) {
            float v = acc[j][t] * inv;
            o[t] = v > 0.f ? v : (__expf(v) - 1.f);
        }
        __half2 p[4];
#pragma unroll
        for (int t = 0; t < 4; t++)
            p[t] = __floats2half2_rn(o[2 * t], o[2 * t + 1]);
        *(uint4*)(xout + (size_t)n * D1 + j * 256 + 8 * lane) = *(uint4*)p;
    }
}

// F=32, H=1: warp per node, 2 nodes per 64-thread block, fp32 z, no ELU.
__global__ void __launch_bounds__(64)
gat_edge32(const int* __restrict__ src,
           const int* __restrict__ offs,
           const float* __restrict__ el,
           const float* __restrict__ er,
           const float* __restrict__ z,
           float* __restrict__ out, int N) {
    const int n    = blockIdx.x * 2 + (threadIdx.x >> 5);
    const int lane = threadIdx.x & 31;
    if (n >= N) return;
    const int s = offs[n], e = offs[n + 1];

    float* op = out + (size_t)n * 32 + lane;
    if (s == e) { *op = 0.f; return; }

    const float er_n = er[n];
    float acc = 0.f, den = 0.f;
    int i = s;
    for (; i + 4 <= e; i += 4) {
        int s0 = __ldg(src + i),     s1 = __ldg(src + i + 1);
        int s2 = __ldg(src + i + 2), s3 = __ldg(src + i + 3);
        float e0 = __ldg(el + s0), e1 = __ldg(el + s1);
        float e2 = __ldg(el + s2), e3 = __ldg(el + s3);
        float v0 = e0 + er_n; v0 = v0 > 0.f ? v0 : 0.2f * v0;
        float v1 = e1 + er_n; v1 = v1 > 0.f ? v1 : 0.2f * v1;
        float v2 = e2 + er_n; v2 = v2 > 0.f ? v2 : 0.2f * v2;
        float v3 = e3 + er_n; v3 = v3 > 0.f ? v3 : 0.2f * v3;
        float w0 = __expf(v0), w1 = __expf(v1);
        float w2 = __expf(v2), w3 = __expf(v3);
        float z0 = z[(size_t)s0 * 32 + lane];
        float z1 = z[(size_t)s1 * 32 + lane];
        float z2 = z[(size_t)s2 * 32 + lane];
        float z3 = z[(size_t)s3 * 32 + lane];
        den += (w0 + w1) + (w2 + w3);
        acc = fmaf(w0, z0, fmaf(w1, z1, fmaf(w2, z2, fmaf(w3, z3, acc))));
    }
    for (; i < e; i++) {
        int s0 = __ldg(src + i);
        float v0 = __ldg(el + s0) + er_n; v0 = v0 > 0.f ? v0 : 0.2f * v0;
        float w0 = __expf(v0);
        den += w0;
        acc = fmaf(w0, z[(size_t)s0 * 32 + lane], acc);
    }
    *op = acc / den;
}

// ---------------------------------------------------------------------------
extern "C" void kernel_launch(void* const* d_in, const int* in_sizes, int n_in,
                              void* d_out, int out_size) {
    const float* h   = (const float*)d_in[0];
    const int*   src = (const int*)  d_in[1];
    const int*   dst = (const int*)  d_in[2];
    const float* W1  = (const float*)d_in[3];
    const float* al1 = (const float*)d_in[4];
    const float* ar1 = (const float*)d_in[5];
    const float* W2  = (const float*)d_in[6];
    const float* al2 = (const float*)d_in[7];
    const float* ar2 = (const float*)d_in[8];
    const float* W3  = (const float*)d_in[9];
    const float* al3 = (const float*)d_in[10];
    const float* ar3 = (const float*)d_in[11];
    float* out = (float*)d_out;

    __half *h16, *w1, *w2, *w3, *z16, *x16;
    float *z3, *el, *er; int* offs;
    cudaGetSymbolAddress((void**)&h16,  g_h16);
    cudaGetSymbolAddress((void**)&w1,   g_w1);
    cudaGetSymbolAddress((void**)&w2,   g_w2);
    cudaGetSymbolAddress((void**)&w3,   g_w3);
    cudaGetSymbolAddress((void**)&z16,  g_z16);
    cudaGetSymbolAddress((void**)&x16,  g_x16);
    cudaGetSymbolAddress((void**)&z3,   g_z3);
    cudaGetSymbolAddress((void**)&el,   g_el);
    cudaGetSymbolAddress((void**)&er,   g_er);
    cudaGetSymbolAddress((void**)&offs, g_offs);

    cudaFuncSetAttribute(gemm_nt_f16<1>,
                         cudaFuncAttributeMaxDynamicSharedMemorySize, GEMM16_SMEM);
    cudaFuncSetAttribute(gemm_nt_f16<2>,
                         cudaFuncAttributeMaxDynamicSharedMemorySize, GEMM16_SMEM);

    const int N = NN;

    setup_all<<<2048, 256>>>(h, W1, W2, W3, h16, w1, w2, w3, dst, offs);

    dim3 g12(D1 / 64, (N + 127) / 128);   // (8, 196)
    dim3 g3(1, (N + 127) / 128);
    const int eb = (N + 1) / 2;           // 2 nodes per 64-thread block

    // ---- layer 1 ----
    gemm_nt_f16<1><<<g12, 256, GEMM16_SMEM>>>(h16, w1, z16, nullptr,
                                              al1, ar1, el, er, N, D1, DIN);
    gat_edge_all<<<eb, 64>>>(src, offs, el, er, z16, x16, N);

    // ---- layer 2 ----
    gemm_nt_f16<1><<<g12, 256, GEMM16_SMEM>>>(x16, w2, z16, nullptr,
                                              al2, ar2, el, er, N, D1, D1);
    gat_edge_all<<<eb, 64>>>(src, offs, el, er, z16, x16, N);

    // ---- layer 3 (H=1, F=32, no ELU, fp32 out; attn fused in epilogue) ----
    gemm_nt_f16<2><<<g3, 256, GEMM16_SMEM>>>(x16, w3, nullptr, z3,
                                             al3, ar3, el, er, N, NCLS, D1);
    gat_edge32<<<eb, 64>>>(src, offs, el, er, z3, out, N);
}